// round 2
// baseline (speedup 1.0000x reference)
#include <cuda_runtime.h>
#include <cuda_bf16.h>

#define B_    8
#define S_    1029
#define D_    1024
#define H_    16
#define HD_   64
#define M_    (B_*S_)     // 8232
#define NPFX  5
#define SCALE_ 0.125f

// Scratch (device globals — no allocation allowed). 16B-aligned for float4 IO.
__device__ __align__(16) float g_q [B_*H_*S_*HD_];   // [b,h,s,d]
__device__ __align__(16) float g_k [B_*H_*S_*HD_];
__device__ __align__(16) float g_v [B_*H_*S_*HD_];
__device__ __align__(16) float g_ao[M_*D_];          // attention out, [m, n]

// ---------------------------------------------------------------------------
// K1: fused QKV projection GEMM. Tile 64x64, BK=16, 4x4 microtile, 256 thr.
// ---------------------------------------------------------------------------
__global__ __launch_bounds__(256) void qkv_gemm(
    const float* __restrict__ x,
    const float* __restrict__ Wq, const float* __restrict__ Wk,
    const float* __restrict__ Wv,
    const float* __restrict__ bq, const float* __restrict__ bv)
{
    __shared__ float As[16][64];        // [k][m]
    __shared__ float Bs[3][16][64];     // [w][k][n]
    const int tid = threadIdx.x;
    const int tx = tid & 15, ty = tid >> 4;
    const int bm = blockIdx.x * 64;
    const int bn = blockIdx.y * 64;

    float aq[4][4] = {}, ak[4][4] = {}, av[4][4] = {};

    for (int k0 = 0; k0 < D_; k0 += 16) {
        {
            int r  = tid >> 2;
            int c4 = (tid & 3) * 4;
            int gm = bm + r;
            float4 val = make_float4(0.f, 0.f, 0.f, 0.f);
            if (gm < M_) val = *(const float4*)(x + (size_t)gm * D_ + k0 + c4);
            As[c4+0][r] = val.x; As[c4+1][r] = val.y;
            As[c4+2][r] = val.z; As[c4+3][r] = val.w;
        }
        {
            int kk = tid >> 4;
            int n4 = (tid & 15) * 4;
            size_t off = (size_t)(k0 + kk) * D_ + bn + n4;
            *(float4*)&Bs[0][kk][n4] = *(const float4*)(Wq + off);
            *(float4*)&Bs[1][kk][n4] = *(const float4*)(Wk + off);
            *(float4*)&Bs[2][kk][n4] = *(const float4*)(Wv + off);
        }
        __syncthreads();
        #pragma unroll
        for (int kk = 0; kk < 16; kk++) {
            float4 a4 = *(float4*)&As[kk][ty*4];
            float4 q4 = *(float4*)&Bs[0][kk][tx*4];
            float4 k4 = *(float4*)&Bs[1][kk][tx*4];
            float4 v4 = *(float4*)&Bs[2][kk][tx*4];
            const float* a = (const float*)&a4;
            const float* qb = (const float*)&q4;
            const float* kb = (const float*)&k4;
            const float* vb = (const float*)&v4;
            #pragma unroll
            for (int i = 0; i < 4; i++)
                #pragma unroll
                for (int j = 0; j < 4; j++) {
                    aq[i][j] = fmaf(a[i], qb[j], aq[i][j]);
                    ak[i][j] = fmaf(a[i], kb[j], ak[i][j]);
                    av[i][j] = fmaf(a[i], vb[j], av[i][j]);
                }
        }
        __syncthreads();
    }

    const int h = blockIdx.y;   // bn = h*64 exactly (one head per block column)
    #pragma unroll
    for (int i = 0; i < 4; i++) {
        int m = bm + ty*4 + i;
        if (m >= M_) continue;
        int b = m / S_, s = m % S_;
        size_t base = (((size_t)(b * H_ + h)) * S_ + s) * HD_;
        #pragma unroll
        for (int j = 0; j < 4; j++) {
            int n = bn + tx*4 + j;
            int d = tx*4 + j;
            g_q[base + d] = aq[i][j] + bq[n];
            g_k[base + d] = ak[i][j];
            g_v[base + d] = av[i][j] + bv[n];
        }
    }
}

// ---------------------------------------------------------------------------
// K2: RoPE (patch tokens only) + q-scale (all tokens).
// ---------------------------------------------------------------------------
__global__ void rope_kernel(const float* __restrict__ cosp,
                            const float* __restrict__ sinp)
{
    const int total = B_*H_*S_*32;
    int i = blockIdx.x * blockDim.x + threadIdx.x;
    if (i >= total) return;
    const bool isQ = (blockIdx.y == 0);
    int dh = i & 31;
    int s  = (i >> 5) % S_;
    int bh = i / (32 * S_);
    float* ptr = (isQ ? g_q : g_k) + ((size_t)bh * S_ + s) * HD_;
    if (s < NPFX) {
        if (isQ) { ptr[dh] *= SCALE_; ptr[dh+32] *= SCALE_; }
        return;
    }
    int p = s - NPFX;
    float c0 = cosp[p*HD_ + dh],      c1 = cosp[p*HD_ + dh + 32];
    float s0 = sinp[p*HD_ + dh],      s1 = sinp[p*HD_ + dh + 32];
    float x0 = ptr[dh], x1 = ptr[dh+32];
    float y0 = x0*c0 - x1*s0;
    float y1 = x1*c1 + x0*s1;
    if (isQ) { y0 *= SCALE_; y1 *= SCALE_; }
    ptr[dh]    = y0;
    ptr[dh+32] = y1;
}

// ---------------------------------------------------------------------------
// K3: fp32 flash attention. One CTA per (b*h, 64-row Q tile).
// Padded smem stride = 68 floats (272B) so float4 row bases stay 16B-aligned.
// ---------------------------------------------------------------------------
#define PADS 68
#define ATT_SMEM_BYTES ((64*PADS*3 + 64*64 + 64*3 + 64*8) * 4)   // 71424

__global__ __launch_bounds__(256) void attn_kernel()
{
    extern __shared__ float sm[];
    float* Qs   = sm;                 // [64][PADS]  (d, m)
    float* Ks   = Qs + 64*PADS;       // [64][PADS]  (d, n)
    float* St   = Ks + 64*PADS;       // [64][PADS]  (n, m)  scores then P
    float* Vs   = St + 64*PADS;       // [64][64]    (n, d)
    float* m_s  = Vs + 64*64;         // [64]
    float* l_s  = m_s + 64;           // [64]
    float* al_s = l_s + 64;           // [64]
    float* redm = al_s + 64;          // [4][64]
    float* reds = redm + 256;         // [4][64]

    const int tid = threadIdx.x;
    const int tx = tid & 15, ty = tid >> 4;
    const int bh = blockIdx.y;
    const int m0 = blockIdx.x * 64;
    const float* qp = g_q + (size_t)bh * S_ * HD_;
    const float* kp = g_k + (size_t)bh * S_ * HD_;
    const float* vp = g_v + (size_t)bh * S_ * HD_;

    #pragma unroll
    for (int t = 0; t < 16; t++) {
        int i  = tid + t * 256;
        int mm = i >> 6, d = i & 63;
        float val = 0.f;
        if (m0 + mm < S_) val = qp[(size_t)(m0 + mm) * HD_ + d];
        Qs[d*PADS + mm] = val;
    }
    if (tid < 64) { m_s[tid] = -1e30f; l_s[tid] = 0.f; }

    float o[4][4] = {};
    const int r = tid & 63, part = tid >> 6;

    for (int n0 = 0; n0 < S_; n0 += 64) {
        __syncthreads();    // also covers Qs/m_s init on first iteration
        #pragma unroll
        for (int t = 0; t < 16; t++) {
            int i  = tid + t * 256;
            int nn = i >> 6, d = i & 63;
            float kv = 0.f, vv = 0.f;
            if (n0 + nn < S_) {
                size_t off = (size_t)(n0 + nn) * HD_ + d;
                kv = kp[off];
                vv = vp[off];
            }
            Ks[d*PADS + nn] = kv;
            Vs[nn*64 + d] = vv;
        }
        __syncthreads();

        // S = Q * K^T  (q already scaled)
        float s_[4][4] = {};
        #pragma unroll
        for (int d = 0; d < 64; d++) {
            float4 a4 = *(float4*)&Qs[d*PADS + ty*4];
            float4 b4 = *(float4*)&Ks[d*PADS + tx*4];
            const float* a = (const float*)&a4;
            const float* b = (const float*)&b4;
            #pragma unroll
            for (int i = 0; i < 4; i++)
                #pragma unroll
                for (int j = 0; j < 4; j++)
                    s_[i][j] = fmaf(a[i], b[j], s_[i][j]);
        }
        // write transposed scores with key mask
        #pragma unroll
        for (int j = 0; j < 4; j++) {
            int n = tx*4 + j;
            bool valid = (n0 + n) < S_;
            #pragma unroll
            for (int i = 0; i < 4; i++)
                St[n*PADS + ty*4 + i] = valid ? s_[i][j] : -1e30f;
        }
        __syncthreads();

        // per-row max
        {
            float pm = -1e30f;
            #pragma unroll
            for (int n = part*16; n < part*16 + 16; n++)
                pm = fmaxf(pm, St[n*PADS + r]);
            redm[part*64 + r] = pm;
        }
        __syncthreads();
        if (part == 0) {
            float nm = fmaxf(fmaxf(redm[r], redm[64+r]),
                             fmaxf(redm[128+r], redm[192+r]));
            nm = fmaxf(nm, m_s[r]);
            al_s[r] = __expf(m_s[r] - nm);
            m_s[r]  = nm;
        }
        __syncthreads();
        // exp in place + partial sums
        {
            float mr = m_s[r];
            float ps = 0.f;
            #pragma unroll
            for (int n = part*16; n < part*16 + 16; n++) {
                float e = __expf(St[n*PADS + r] - mr);
                St[n*PADS + r] = e;
                ps += e;
            }
            reds[part*64 + r] = ps;
        }
        __syncthreads();
        if (part == 0)
            l_s[r] = l_s[r]*al_s[r] + reds[r] + reds[64+r] + reds[128+r] + reds[192+r];

        // O = O*alpha + P * V
        {
            float alpha[4];
            #pragma unroll
            for (int i = 0; i < 4; i++) alpha[i] = al_s[ty*4 + i];
            #pragma unroll
            for (int i = 0; i < 4; i++)
                #pragma unroll
                for (int j = 0; j < 4; j++)
                    o[i][j] *= alpha[i];
            #pragma unroll
            for (int n = 0; n < 64; n++) {
                float4 p4 = *(float4*)&St[n*PADS + ty*4];
                float4 v4 = *(float4*)&Vs[n*64 + tx*4];
                const float* p = (const float*)&p4;
                const float* v = (const float*)&v4;
                #pragma unroll
                for (int i = 0; i < 4; i++)
                    #pragma unroll
                    for (int j = 0; j < 4; j++)
                        o[i][j] = fmaf(p[i], v[j], o[i][j]);
            }
        }
    }
    __syncthreads();   // make final l_s visible

    const int b = bh / H_, h = bh % H_;
    #pragma unroll
    for (int i = 0; i < 4; i++) {
        int mm = m0 + ty*4 + i;
        if (mm >= S_) continue;
        float inv = 1.f / l_s[ty*4 + i];
        size_t base = ((size_t)b * S_ + mm) * D_ + h * HD_ + tx*4;
        #pragma unroll
        for (int j = 0; j < 4; j++)
            g_ao[base + j] = o[i][j] * inv;
    }
}

// ---------------------------------------------------------------------------
// K4: output projection GEMM + bias.
// ---------------------------------------------------------------------------
__global__ __launch_bounds__(256) void out_gemm(
    const float* __restrict__ Wo, const float* __restrict__ bo,
    float* __restrict__ out)
{
    __shared__ float As[16][64];
    __shared__ float Bs[16][64];
    const int tid = threadIdx.x;
    const int tx = tid & 15, ty = tid >> 4;
    const int bm = blockIdx.x * 64;
    const int bn = blockIdx.y * 64;

    float acc[4][4] = {};
    for (int k0 = 0; k0 < D_; k0 += 16) {
        {
            int r  = tid >> 2;
            int c4 = (tid & 3) * 4;
            int gm = bm + r;
            float4 val = make_float4(0.f, 0.f, 0.f, 0.f);
            if (gm < M_) val = *(const float4*)(g_ao + (size_t)gm * D_ + k0 + c4);
            As[c4+0][r] = val.x; As[c4+1][r] = val.y;
            As[c4+2][r] = val.z; As[c4+3][r] = val.w;
        }
        {
            int kk = tid >> 4;
            int n4 = (tid & 15) * 4;
            *(float4*)&Bs[kk][n4] =
                *(const float4*)(Wo + (size_t)(k0 + kk) * D_ + bn + n4);
        }
        __syncthreads();
        #pragma unroll
        for (int kk = 0; kk < 16; kk++) {
            float4 a4 = *(float4*)&As[kk][ty*4];
            float4 b4 = *(float4*)&Bs[kk][tx*4];
            const float* a = (const float*)&a4;
            const float* b = (const float*)&b4;
            #pragma unroll
            for (int i = 0; i < 4; i++)
                #pragma unroll
                for (int j = 0; j < 4; j++)
                    acc[i][j] = fmaf(a[i], b[j], acc[i][j]);
        }
        __syncthreads();
    }
    #pragma unroll
    for (int i = 0; i < 4; i++) {
        int m = bm + ty*4 + i;
        if (m >= M_) continue;
        #pragma unroll
        for (int j = 0; j < 4; j++) {
            int n = bn + tx*4 + j;
            out[(size_t)m * D_ + n] = acc[i][j] + bo[n];
        }
    }
}

// ---------------------------------------------------------------------------
extern "C" void kernel_launch(void* const* d_in, const int* in_sizes, int n_in,
                              void* d_out, int out_size)
{
    const float* x        = (const float*)d_in[0];
    const float* rope_cos = (const float*)d_in[1];
    const float* rope_sin = (const float*)d_in[2];
    const float* Wq       = (const float*)d_in[3];
    const float* bq       = (const float*)d_in[4];
    const float* Wk       = (const float*)d_in[5];
    const float* Wv       = (const float*)d_in[6];
    const float* bv       = (const float*)d_in[7];
    const float* Wo       = (const float*)d_in[8];
    const float* bo       = (const float*)d_in[9];
    float* out = (float*)d_out;

    cudaFuncSetAttribute(attn_kernel,
        cudaFuncAttributeMaxDynamicSharedMemorySize, ATT_SMEM_BYTES);

    dim3 g1((M_ + 63) / 64, D_ / 64);          // 129 x 16
    qkv_gemm<<<g1, 256>>>(x, Wq, Wk, Wv, bq, bv);

    int pairs = B_*H_*S_*32;
    dim3 g2((pairs + 255) / 256, 2);
    rope_kernel<<<g2, 256>>>(rope_cos, rope_sin);

    dim3 g3((S_ + 63) / 64, B_*H_);            // 17 x 128
    attn_kernel<<<g3, 256, ATT_SMEM_BYTES>>>();

    dim3 g4((M_ + 63) / 64, D_ / 64);
    out_gemm<<<g4, 256>>>(Wo, bo, out);
}